// round 4
// baseline (speedup 1.0000x reference)
#include <cuda_runtime.h>
#include <float.h>

#define BB 2
#define HH 12
#define NN 1600
#define DD 32
#define GG 48
#define KT 96
#define CC 384
#define BHc (BB*HH)          // 24
#define NQ (BHc*NN)          // 38400
#define NROW (BHc*GG)        // 1152

// Scratch (no cudaMalloc allowed)
__device__ float g_qkv[3][BHc*NN*DD];      // [which][b*h][n][d]
__device__ int   g_gidx[NQ];
__device__ float g_qsum[NROW*DD];
__device__ int   g_cnt[NROW];
__device__ int   g_topk[NROW*KT];
__device__ int   g_qlist[NROW*NN];         // query indices per (bh,g)
__device__ float g_att[BB*NN*HH*DD];       // [b][n][h][d]

__global__ void zero_kernel() {
    int i = blockIdx.x*blockDim.x + threadIdx.x;
    if (i < NROW*DD) g_qsum[i] = 0.f;
    if (i < NROW)    g_cnt[i] = 0;
}

__device__ __forceinline__ unsigned long long ffma2(
    unsigned long long a, unsigned long long b, unsigned long long c) {
    asm("fma.rn.f32x2 %0, %1, %2, %0;" : "+l"(c) : "l"(a), "l"(b));
    return c;
}

// out[m][col] = sum_k A[m][k] * B[col][k]   (NT GEMM, K=384, M=3200)
// MODE 0: A = x, scatter into g_qkv.  MODE 1: A = g_att, write d_out.
// f32x2 packed-FMA microkernel, double-buffered k-tiles.
template<int MODE>
__global__ void gemm_nt(const float* __restrict__ A, const float* __restrict__ B,
                        float* __restrict__ out) {
    const int K = CC;
    __shared__ float2 As2[2][16][128];   // duplicated a: (a,a) — 2 x 16KB
    __shared__ float  Bs [2][16][128];   // 2 x 8KB   (total 48KB)
    const float* Ap = (MODE == 0) ? A : (const float*)g_att;
    int m0 = blockIdx.y * 128, n0 = blockIdx.x * 128;
    int tid = threadIdx.x;
    int tx = tid & 15, ty = tid >> 4;

    unsigned long long acc2[8][4];
    #pragma unroll
    for (int i = 0; i < 8; i++)
        #pragma unroll
        for (int j = 0; j < 4; j++) acc2[i][j] = 0ull;

    // per-iteration load mapping: two slots per thread
    int r0 = tid >> 2,        c40 = (tid & 3) << 2;
    int r1 = (tid + 256) >> 2, c41 = ((tid + 256) & 3) << 2;

    float4 va0, va1, vb0, vb1;
    // prologue: tile 0
    va0 = *(const float4*)(Ap + (size_t)(m0 + r0)*K + c40);
    va1 = *(const float4*)(Ap + (size_t)(m0 + r1)*K + c41);
    vb0 = *(const float4*)(B  + (size_t)(n0 + r0)*K + c40);
    vb1 = *(const float4*)(B  + (size_t)(n0 + r1)*K + c41);
    {
        As2[0][c40+0][r0] = make_float2(va0.x, va0.x);
        As2[0][c40+1][r0] = make_float2(va0.y, va0.y);
        As2[0][c40+2][r0] = make_float2(va0.z, va0.z);
        As2[0][c40+3][r0] = make_float2(va0.w, va0.w);
        As2[0][c41+0][r1] = make_float2(va1.x, va1.x);
        As2[0][c41+1][r1] = make_float2(va1.y, va1.y);
        As2[0][c41+2][r1] = make_float2(va1.z, va1.z);
        As2[0][c41+3][r1] = make_float2(va1.w, va1.w);
        Bs[0][c40+0][r0] = vb0.x; Bs[0][c40+1][r0] = vb0.y;
        Bs[0][c40+2][r0] = vb0.z; Bs[0][c40+3][r0] = vb0.w;
        Bs[0][c41+0][r1] = vb1.x; Bs[0][c41+1][r1] = vb1.y;
        Bs[0][c41+2][r1] = vb1.z; Bs[0][c41+3][r1] = vb1.w;
    }
    __syncthreads();

    const int NT = K / 16;   // 24
    for (int kt = 0; kt < NT; kt++) {
        int buf = kt & 1;
        if (kt + 1 < NT) {
            int k0 = (kt + 1) * 16;
            va0 = *(const float4*)(Ap + (size_t)(m0 + r0)*K + k0 + c40);
            va1 = *(const float4*)(Ap + (size_t)(m0 + r1)*K + k0 + c41);
            vb0 = *(const float4*)(B  + (size_t)(n0 + r0)*K + k0 + c40);
            vb1 = *(const float4*)(B  + (size_t)(n0 + r1)*K + k0 + c41);
        }
        #pragma unroll
        for (int kk = 0; kk < 16; kk++) {
            double2 a01 = *(const double2*)&As2[buf][kk][ty*8 + 0];
            double2 a23 = *(const double2*)&As2[buf][kk][ty*8 + 2];
            double2 a45 = *(const double2*)&As2[buf][kk][ty*8 + 4];
            double2 a67 = *(const double2*)&As2[buf][kk][ty*8 + 6];
            double2 bA  = *(const double2*)&Bs[buf][kk][tx*8 + 0];
            double2 bB  = *(const double2*)&Bs[buf][kk][tx*8 + 4];
            unsigned long long a2[8], b2[4];
            a2[0] = __double_as_longlong(a01.x); a2[1] = __double_as_longlong(a01.y);
            a2[2] = __double_as_longlong(a23.x); a2[3] = __double_as_longlong(a23.y);
            a2[4] = __double_as_longlong(a45.x); a2[5] = __double_as_longlong(a45.y);
            a2[6] = __double_as_longlong(a67.x); a2[7] = __double_as_longlong(a67.y);
            b2[0] = __double_as_longlong(bA.x);  b2[1] = __double_as_longlong(bA.y);
            b2[2] = __double_as_longlong(bB.x);  b2[3] = __double_as_longlong(bB.y);
            #pragma unroll
            for (int i = 0; i < 8; i++)
                #pragma unroll
                for (int j = 0; j < 4; j++)
                    acc2[i][j] = ffma2(a2[i], b2[j], acc2[i][j]);
        }
        if (kt + 1 < NT) {
            int nb = buf ^ 1;
            As2[nb][c40+0][r0] = make_float2(va0.x, va0.x);
            As2[nb][c40+1][r0] = make_float2(va0.y, va0.y);
            As2[nb][c40+2][r0] = make_float2(va0.z, va0.z);
            As2[nb][c40+3][r0] = make_float2(va0.w, va0.w);
            As2[nb][c41+0][r1] = make_float2(va1.x, va1.x);
            As2[nb][c41+1][r1] = make_float2(va1.y, va1.y);
            As2[nb][c41+2][r1] = make_float2(va1.z, va1.z);
            As2[nb][c41+3][r1] = make_float2(va1.w, va1.w);
            Bs[nb][c40+0][r0] = vb0.x; Bs[nb][c40+1][r0] = vb0.y;
            Bs[nb][c40+2][r0] = vb0.z; Bs[nb][c40+3][r0] = vb0.w;
            Bs[nb][c41+0][r1] = vb1.x; Bs[nb][c41+1][r1] = vb1.y;
            Bs[nb][c41+2][r1] = vb1.z; Bs[nb][c41+3][r1] = vb1.w;
            __syncthreads();
        }
    }

    #pragma unroll
    for (int i = 0; i < 8; i++) {
        int m = m0 + ty*8 + i;
        int bi = m / NN, n = m % NN;
        #pragma unroll
        for (int j = 0; j < 4; j++) {
            float lo = __uint_as_float((unsigned)(acc2[i][j] & 0xffffffffu));
            float hi = __uint_as_float((unsigned)(acc2[i][j] >> 32));
            #pragma unroll
            for (int q = 0; q < 2; q++) {
                float v = q ? hi : lo;
                int col = n0 + tx*8 + 2*j + q;
                if (MODE == 0) {
                    int which = col / (HH*DD);
                    int r2 = col % (HH*DD);
                    int head = r2 / DD, dd = r2 % DD;
                    g_qkv[which][(((size_t)bi*HH + head)*NN + n)*DD + dd] = v;
                } else {
                    out[(size_t)m*(HH*DD) + col] = v;
                }
            }
        }
    }
}

// One warp per query. Lane-per-group argmax (first-max tie-break = jnp.argmax),
// accumulate group sums/counts, append query to its group's list.
__global__ void route_kernel(const float* __restrict__ w_gp) {
    __shared__ float sgp[GG][33];
    int tid = threadIdx.x;
    int qid = blockIdx.x * 8 + (tid >> 5);
    int lane = tid & 31;
    int bh = qid / NN, n = qid % NN;
    int h = bh % HH;
    for (int i = tid; i < GG*DD; i += 256)
        sgp[i >> 5][i & 31] = w_gp[h*GG*DD + i];
    __syncthreads();
    float qv = g_qkv[0][((size_t)bh*NN + n)*DD + lane];
    float s0 = 0.f, s1 = 0.f;
    #pragma unroll
    for (int d = 0; d < DD; d++) {
        float qd = __shfl_sync(0xffffffffu, qv, d);
        s0 += qd * sgp[lane][d];
        if (lane < 16) s1 += qd * sgp[lane + 32][d];
    }
    float bv = s0; int bg = lane;
    if (lane < 16 && (s1 > bv)) { bv = s1; bg = lane + 32; }
    #pragma unroll
    for (int o = 16; o; o >>= 1) {
        float ov = __shfl_xor_sync(0xffffffffu, bv, o);
        int   og = __shfl_xor_sync(0xffffffffu, bg, o);
        if (ov > bv || (ov == bv && og < bg)) { bv = ov; bg = og; }
    }
    bg = __shfl_sync(0xffffffffu, bg, 0);
    int row = bh*GG + bg;
    if (lane == 0) {
        g_gidx[qid] = bg;
        int p = atomicAdd(&g_cnt[row], 1);
        g_qlist[row*NN + p] = n;
    }
    atomicAdd(&g_qsum[row*DD + lane], qv);
}

__device__ __forceinline__ unsigned f2u_mono(float f) {
    unsigned u = __float_as_uint(f);
    return u ^ (((int)u >> 31) | 0x80000000u);
}

// One block per (bh, GPB groups): fold qmean, compute qmw scores, radix-select top-96.
// Empty groups are skipped entirely (their topk list is never consumed).
#define GPB 2
__global__ void qmw_topk_kernel() {
    int blk = blockIdx.x;                 // [0, BHc * GG/GPB)
    int bh = blk / (GG/GPB);
    int g0 = (blk % (GG/GPB)) * GPB;
    __shared__ float qm[GPB][DD];
    __shared__ unsigned uv[GPB][NN];
    __shared__ unsigned hist[256];
    __shared__ int s_selb, s_k, s_nout;
    __shared__ int warp_sums[8];
    __shared__ int s_cnt[GPB];
    int tid = threadIdx.x, lane = tid & 31, w = tid >> 5;

    if (tid < GPB) s_cnt[tid] = g_cnt[bh*GG + g0 + tid];
    if (tid < GPB*DD) {
        int row = bh*GG + g0 + tid/DD;
        float c = (float)g_cnt[row];
        qm[tid/DD][tid & 31] = g_qsum[row*DD + (tid & 31)] / fmaxf(c, 1e-8f);
    }
    __syncthreads();

    const float* kb = &g_qkv[1][(size_t)bh*NN*DD];
    for (int m = tid; m < NN; m += 256) {
        float kr[DD];
        #pragma unroll
        for (int t = 0; t < 8; t++) {
            float4 v = *(const float4*)(kb + (size_t)m*DD + 4*t);
            kr[4*t] = v.x; kr[4*t+1] = v.y; kr[4*t+2] = v.z; kr[4*t+3] = v.w;
        }
        #pragma unroll
        for (int g = 0; g < GPB; g++) {
            float s = 0.f;
            #pragma unroll
            for (int d = 0; d < DD; d++) s += qm[g][d] * kr[d];
            uv[g][m] = f2u_mono(s);
        }
    }
    __syncthreads();

    for (int g = 0; g < GPB; g++) {
        if (s_cnt[g] == 0) continue;      // uniform across block: group unused
        int row = bh*GG + g0 + g;
        unsigned prefix = 0;
        int k = KT;
        #pragma unroll
        for (int pass = 0; pass < 4; pass++) {
            int shift = 24 - 8*pass;
            hist[tid] = 0;
            __syncthreads();
            for (int m = tid; m < NN; m += 256) {
                unsigned u = uv[g][m];
                bool cand = (pass == 0) || ((u >> (shift+8)) == (prefix >> (shift+8)));
                if (cand) atomicAdd(&hist[(u >> shift) & 255], 1u);
            }
            __syncthreads();
            if (tid < 32) {
                unsigned hv[8], loc[8];
                unsigned s = 0;
                #pragma unroll
                for (int i = 7; i >= 0; i--) {
                    hv[i] = hist[lane*8 + i];
                    s += hv[i];
                    loc[i] = s;
                }
                unsigned run = s;
                #pragma unroll
                for (int o = 1; o < 32; o <<= 1) {
                    unsigned t = __shfl_down_sync(0xffffffffu, run, o);
                    if (lane + o < 32) run += t;
                }
                unsigned above = run - s;
                #pragma unroll
                for (int i = 0; i < 8; i++) {
                    unsigned S  = above + loc[i];
                    unsigned gt = S - hv[i];
                    if ((unsigned)k <= S && (unsigned)k > gt) {
                        s_selb = lane*8 + i;
                        s_k    = k - (int)gt;
                    }
                }
            }
            __syncthreads();
            prefix |= (unsigned)s_selb << shift;
            k = s_k;
            __syncthreads();
        }
        unsigned uT = prefix;
        int k_rem = k;
        if (tid == 0) s_nout = 0;
        __syncthreads();
        for (int m = tid; m < NN; m += 256) {
            if (uv[g][m] > uT) {
                int p = atomicAdd(&s_nout, 1);
                g_topk[row*KT + p] = m;
            }
        }
        __syncthreads();
        int base = s_nout;
        const int CH = (NN + 255) / 256;
        int lo = tid * CH;
        int hi = lo + CH; if (hi > NN) hi = NN; if (lo > NN) lo = NN;
        int c_loc = 0;
        for (int m = lo; m < hi; m++) if (uv[g][m] == uT) c_loc++;
        int v = c_loc;
        #pragma unroll
        for (int o = 1; o < 32; o <<= 1) {
            int t = __shfl_up_sync(0xffffffffu, v, o);
            if (lane >= o) v += t;
        }
        if (lane == 31) warp_sums[w] = v;
        __syncthreads();
        int woff = 0;
        #pragma unroll
        for (int ww = 0; ww < 8; ww++) if (ww < w) woff += warp_sums[ww];
        int rank = woff + v - c_loc;
        for (int m = lo; m < hi; m++) {
            if (uv[g][m] == uT) {
                if (rank < k_rem) g_topk[row*KT + base + rank] = m;
                rank++;
            }
        }
        __syncthreads();
    }
}

// One block per (bh,g): stage the group's 96 K/V rows in smem, then each warp
// processes queries of the group: scores + softmax + weighted V sum.
__global__ void attn_kernel() {
    int row = blockIdx.x;              // [0, NROW)
    int cnt = g_cnt[row];
    if (cnt == 0) return;
    int bh = row / GG;
    int bi = bh / HH, h = bh % HH;
    __shared__ float Kt[DD][97];       // [d][key]
    __shared__ float Vs[KT][33];       // [key][d]
    int tid = threadIdx.x, w = tid >> 5, lane = tid & 31;
    const int* tk = &g_topk[row*KT];
    const float* kb = &g_qkv[1][(size_t)bh*NN*DD];
    const float* vb = &g_qkv[2][(size_t)bh*NN*DD];
    for (int j = w; j < KT; j += 8) {
        int idx = tk[j];
        Kt[lane][j] = kb[(size_t)idx*DD + lane];
        Vs[j][lane] = vb[(size_t)idx*DD + lane];
    }
    __syncthreads();
    const int* ql = &g_qlist[row*NN];
    const float* qb = &g_qkv[0][(size_t)bh*NN*DD];
    const float scale = 0.17677669529663687f;  // 32^-0.5
    for (int i = w; i < cnt; i += 8) {
        int n = ql[i];
        float qv = qb[(size_t)n*DD + lane];
        float s0 = 0.f, s1 = 0.f, s2 = 0.f;
        #pragma unroll
        for (int d = 0; d < DD; d++) {
            float qd = __shfl_sync(0xffffffffu, qv, d);
            s0 += qd * Kt[d][lane];
            s1 += qd * Kt[d][lane + 32];
            s2 += qd * Kt[d][lane + 64];
        }
        s0 *= scale; s1 *= scale; s2 *= scale;
        float mx = fmaxf(s0, fmaxf(s1, s2));
        #pragma unroll
        for (int o = 16; o; o >>= 1) mx = fmaxf(mx, __shfl_xor_sync(0xffffffffu, mx, o));
        float e0 = __expf(s0 - mx), e1 = __expf(s1 - mx), e2 = __expf(s2 - mx);
        float ps = e0 + e1 + e2;
        #pragma unroll
        for (int o = 16; o; o >>= 1) ps += __shfl_xor_sync(0xffffffffu, ps, o);
        float inv = 1.f / ps;
        float acc = 0.f;
        #pragma unroll
        for (int j = 0; j < KT; j++) {
            float pj = __shfl_sync(0xffffffffu, (j < 32) ? e0 : ((j < 64) ? e1 : e2), j & 31);
            acc += pj * Vs[j][lane];
        }
        acc *= inv;
        g_att[(((size_t)bi*NN + n)*HH + h)*DD + lane] = acc;
    }
}

extern "C" void kernel_launch(void* const* d_in, const int* in_sizes, int n_in,
                              void* d_out, int out_size) {
    const float* x      = (const float*)d_in[0];
    const float* w_qkv  = (const float*)d_in[1];
    const float* w_gp   = (const float*)d_in[2];
    const float* w_proj = (const float*)d_in[3];
    float* out = (float*)d_out;

    zero_kernel<<<144, 256>>>();
    gemm_nt<0><<<dim3(9, 25), 256>>>(x, w_qkv, nullptr);       // QKV: 3200x1152x384
    route_kernel<<<NQ/8, 256>>>(w_gp);
    qmw_topk_kernel<<<BHc*(GG/GPB), 256>>>();
    attn_kernel<<<NROW, 256>>>();
    gemm_nt<1><<<dim3(3, 25), 256>>>(nullptr, w_proj, out);    // proj: 3200x384x384
}

// round 5
// speedup vs baseline: 1.0112x; 1.0112x over previous
#include <cuda_runtime.h>
#include <float.h>

#define BB 2
#define HH 12
#define NN 1600
#define DD 32
#define GG 48
#define KT 96
#define CC 384
#define BHc (BB*HH)          // 24
#define NQ (BHc*NN)          // 38400
#define NROW (BHc*GG)        // 1152

// Scratch (no cudaMalloc allowed)
__device__ float g_qkv[3][BHc*NN*DD];      // [which][b*h][n][d]
__device__ int   g_gidx[NQ];
__device__ float g_qsum[NROW*DD];
__device__ int   g_cnt[NROW];
__device__ int   g_topk[NROW*KT];
__device__ int   g_qlist[NROW*NN];         // query indices per (bh,g)
__device__ float g_att[BB*NN*HH*DD];       // [b][n][h][d]

__global__ void zero_kernel() {
    int i = blockIdx.x*blockDim.x + threadIdx.x;
    if (i < NROW*DD) g_qsum[i] = 0.f;
    if (i < NROW)    g_cnt[i] = 0;
}

// out[m][col] = sum_k A[m][k] * B[col][k]   (NT GEMM, K=384, M=3200)
// MODE 0: A = x, scatter into g_qkv.  MODE 1: A = g_att, write d_out.
template<int MODE>
__global__ void gemm_nt(const float* __restrict__ A, const float* __restrict__ B,
                        float* __restrict__ out) {
    const int K = CC;
    __shared__ float As[16][128];
    __shared__ float Bs[16][128];
    const float* Ap = (MODE == 0) ? A : (const float*)g_att;
    int m0 = blockIdx.y * 128, n0 = blockIdx.x * 128;
    int tid = threadIdx.x;
    int tx = tid & 15, ty = tid >> 4;
    float acc[8][8] = {};
    for (int k0 = 0; k0 < K; k0 += 16) {
        #pragma unroll
        for (int s = 0; s < 2; s++) {
            int slot = tid + s * 256;
            int r = slot >> 2, c4 = (slot & 3) << 2;
            float4 va = *(const float4*)(Ap + (size_t)(m0 + r)*K + k0 + c4);
            As[c4+0][r] = va.x; As[c4+1][r] = va.y; As[c4+2][r] = va.z; As[c4+3][r] = va.w;
            float4 vb = *(const float4*)(B + (size_t)(n0 + r)*K + k0 + c4);
            Bs[c4+0][r] = vb.x; Bs[c4+1][r] = vb.y; Bs[c4+2][r] = vb.z; Bs[c4+3][r] = vb.w;
        }
        __syncthreads();
        #pragma unroll
        for (int kk = 0; kk < 16; kk++) {
            float a[8], b[8];
            *(float4*)&a[0] = *(const float4*)&As[kk][ty*8];
            *(float4*)&a[4] = *(const float4*)&As[kk][ty*8+4];
            *(float4*)&b[0] = *(const float4*)&Bs[kk][tx*8];
            *(float4*)&b[4] = *(const float4*)&Bs[kk][tx*8+4];
            #pragma unroll
            for (int i = 0; i < 8; i++)
                #pragma unroll
                for (int j = 0; j < 8; j++)
                    acc[i][j] += a[i] * b[j];
        }
        __syncthreads();
    }
    #pragma unroll
    for (int i = 0; i < 8; i++) {
        int m = m0 + ty*8 + i;
        int bi = m / NN, n = m % NN;
        #pragma unroll
        for (int j = 0; j < 8; j++) {
            int col = n0 + tx*8 + j;
            if (MODE == 0) {
                int which = col / (HH*DD);
                int r2 = col % (HH*DD);
                int head = r2 / DD, dd = r2 % DD;
                g_qkv[which][(((size_t)bi*HH + head)*NN + n)*DD + dd] = acc[i][j];
            } else {
                out[(size_t)m*(HH*DD) + col] = acc[i][j];
            }
        }
    }
}

// One warp per query. Lane-per-group argmax (first-max tie-break = jnp.argmax),
// accumulate group sums/counts, append query to its group's list.
__global__ void route_kernel(const float* __restrict__ w_gp) {
    __shared__ float sgp[GG][33];
    int tid = threadIdx.x;
    int qid = blockIdx.x * 8 + (tid >> 5);
    int lane = tid & 31;
    int bh = qid / NN, n = qid % NN;
    int h = bh % HH;
    for (int i = tid; i < GG*DD; i += 256)
        sgp[i >> 5][i & 31] = w_gp[h*GG*DD + i];
    __syncthreads();
    float qv = g_qkv[0][((size_t)bh*NN + n)*DD + lane];
    float s0 = 0.f, s1 = 0.f;
    #pragma unroll
    for (int d = 0; d < DD; d++) {
        float qd = __shfl_sync(0xffffffffu, qv, d);
        s0 += qd * sgp[lane][d];
        if (lane < 16) s1 += qd * sgp[lane + 32][d];
    }
    float bv = s0; int bg = lane;
    if (lane < 16 && (s1 > bv)) { bv = s1; bg = lane + 32; }
    #pragma unroll
    for (int o = 16; o; o >>= 1) {
        float ov = __shfl_xor_sync(0xffffffffu, bv, o);
        int   og = __shfl_xor_sync(0xffffffffu, bg, o);
        if (ov > bv || (ov == bv && og < bg)) { bv = ov; bg = og; }
    }
    bg = __shfl_sync(0xffffffffu, bg, 0);
    int row = bh*GG + bg;
    if (lane == 0) {
        g_gidx[qid] = bg;
        int p = atomicAdd(&g_cnt[row], 1);
        g_qlist[row*NN + p] = n;
    }
    atomicAdd(&g_qsum[row*DD + lane], qv);
}

__device__ __forceinline__ unsigned f2u_mono(float f) {
    unsigned u = __float_as_uint(f);
    return u ^ (((int)u >> 31) | 0x80000000u);
}

// One block per (bh, GPB groups): fold qmean, compute qmw scores, radix-select top-96.
// Empty groups are skipped entirely (their topk list is never consumed).
// Warp-aggregated (match_any) histogram + double-buffered hist (2 barriers/pass).
#define GPB 2
__global__ void qmw_topk_kernel() {
    int blk = blockIdx.x;                 // [0, BHc * GG/GPB)
    int bh = blk / (GG/GPB);
    int g0 = (blk % (GG/GPB)) * GPB;
    __shared__ float qm[GPB][DD];
    __shared__ unsigned uv[GPB][NN];
    __shared__ unsigned hist2[2][256];
    __shared__ int s_selb, s_k, s_nout;
    __shared__ int warp_sums[8];
    __shared__ int s_cnt[GPB];
    int tid = threadIdx.x, lane = tid & 31, w = tid >> 5;

    if (tid < GPB) s_cnt[tid] = g_cnt[bh*GG + g0 + tid];
    if (tid < GPB*DD) {
        int row = bh*GG + g0 + tid/DD;
        float c = (float)g_cnt[row];
        qm[tid/DD][tid & 31] = g_qsum[row*DD + (tid & 31)] / fmaxf(c, 1e-8f);
    }
    hist2[0][tid] = 0;                    // pass-0 buffer; parity self-maintains after
    __syncthreads();

    const float* kb = &g_qkv[1][(size_t)bh*NN*DD];
    for (int m = tid; m < NN; m += 256) {
        float kr[DD];
        #pragma unroll
        for (int t = 0; t < 8; t++) {
            float4 v = *(const float4*)(kb + (size_t)m*DD + 4*t);
            kr[4*t] = v.x; kr[4*t+1] = v.y; kr[4*t+2] = v.z; kr[4*t+3] = v.w;
        }
        #pragma unroll
        for (int g = 0; g < GPB; g++) {
            float s = 0.f;
            #pragma unroll
            for (int d = 0; d < DD; d++) s += qm[g][d] * kr[d];
            uv[g][m] = f2u_mono(s);
        }
    }
    __syncthreads();

    for (int g = 0; g < GPB; g++) {
        if (s_cnt[g] == 0) continue;      // uniform across block: group unused
        int row = bh*GG + g0 + g;
        unsigned prefix = 0;
        int k = KT;
        #pragma unroll
        for (int pass = 0; pass < 4; pass++) {
            int cur = pass & 1;
            int shift = 24 - 8*pass;
            // warp-aggregated histogram accumulate
            #pragma unroll
            for (int it = 0; it < 7; it++) {      // 7*256 >= NN, uniform trip count
                int m = tid + it*256;
                unsigned u = (m < NN) ? uv[g][m] : 0u;
                bool cand = (m < NN) &&
                            ((pass == 0) || ((u >> (shift+8)) == (prefix >> (shift+8))));
                unsigned bin = cand ? ((u >> shift) & 255u) : 256u;  // 256 = sentinel
                unsigned grp = __match_any_sync(0xffffffffu, bin);
                int leader = __ffs(grp) - 1;
                if (cand && lane == leader)
                    atomicAdd(&hist2[cur][bin], (unsigned)__popc(grp));
            }
            __syncthreads();
            if (w == 0) {
                // lane owns bins [lane*8, lane*8+8): within-lane suffix sums
                unsigned hv[8], loc[8];
                unsigned s = 0;
                #pragma unroll
                for (int i = 7; i >= 0; i--) {
                    hv[i] = hist2[cur][lane*8 + i];
                    s += hv[i];
                    loc[i] = s;
                }
                unsigned run = s;
                #pragma unroll
                for (int o = 1; o < 32; o <<= 1) {
                    unsigned t = __shfl_down_sync(0xffffffffu, run, o);
                    if (lane + o < 32) run += t;
                }
                unsigned above = run - s;  // count in lanes > me
                #pragma unroll
                for (int i = 0; i < 8; i++) {
                    unsigned S  = above + loc[i];           // count >= bin
                    unsigned gt = S - hv[i];                // count > bin
                    if ((unsigned)k <= S && (unsigned)k > gt) {
                        s_selb = lane*8 + i;
                        s_k    = k - (int)gt;
                    }
                }
            } else {
                // zero the other buffer for the next pass / next group
                for (int i = tid - 32; i < 256; i += 224) hist2[cur ^ 1][i] = 0;
            }
            __syncthreads();
            prefix |= (unsigned)s_selb << shift;
            k = s_k;
        }
        unsigned uT = prefix;
        int k_rem = k;
        if (tid == 0) s_nout = 0;
        __syncthreads();
        // strictly-greater: order in g_topk is irrelevant (mask semantics)
        for (int m = tid; m < NN; m += 256) {
            if (uv[g][m] > uT) {
                int p = atomicAdd(&s_nout, 1);
                g_topk[row*KT + p] = m;
            }
        }
        __syncthreads();
        int base = s_nout;                 // == KT - k_rem
        // equals: keep the k_rem LOWEST indices (lax.top_k stable tie-break).
        const int CH = (NN + 255) / 256;   // 7
        int lo = tid * CH;
        int hi = lo + CH; if (hi > NN) hi = NN; if (lo > NN) lo = NN;
        int c_loc = 0;
        for (int m = lo; m < hi; m++) if (uv[g][m] == uT) c_loc++;
        int v = c_loc;
        #pragma unroll
        for (int o = 1; o < 32; o <<= 1) {
            int t = __shfl_up_sync(0xffffffffu, v, o);
            if (lane >= o) v += t;
        }
        if (lane == 31) warp_sums[w] = v;
        __syncthreads();
        int woff = 0;
        #pragma unroll
        for (int ww = 0; ww < 8; ww++) if (ww < w) woff += warp_sums[ww];
        int rank = woff + v - c_loc;
        for (int m = lo; m < hi; m++) {
            if (uv[g][m] == uT) {
                if (rank < k_rem) g_topk[row*KT + base + rank] = m;
                rank++;
            }
        }
        __syncthreads();
    }
}

// One block per (bh,g): stage the group's 96 K/V rows in smem, then each warp
// processes queries of the group: scores + softmax + weighted V sum.
__global__ void attn_kernel() {
    int row = blockIdx.x;              // [0, NROW)
    int cnt = g_cnt[row];
    if (cnt == 0) return;
    int bh = row / GG;
    int bi = bh / HH, h = bh % HH;
    __shared__ float Kt[DD][97];       // [d][key]
    __shared__ float Vs[KT][33];       // [key][d]
    int tid = threadIdx.x, w = tid >> 5, lane = tid & 31;
    const int* tk = &g_topk[row*KT];
    const float* kb = &g_qkv[1][(size_t)bh*NN*DD];
    const float* vb = &g_qkv[2][(size_t)bh*NN*DD];
    for (int j = w; j < KT; j += 8) {
        int idx = tk[j];
        Kt[lane][j] = kb[(size_t)idx*DD + lane];
        Vs[j][lane] = vb[(size_t)idx*DD + lane];
    }
    __syncthreads();
    const int* ql = &g_qlist[row*NN];
    const float* qb = &g_qkv[0][(size_t)bh*NN*DD];
    const float scale = 0.17677669529663687f;  // 32^-0.5
    for (int i = w; i < cnt; i += 8) {
        int n = ql[i];
        float qv = qb[(size_t)n*DD + lane];
        float s0 = 0.f, s1 = 0.f, s2 = 0.f;
        #pragma unroll
        for (int d = 0; d < DD; d++) {
            float qd = __shfl_sync(0xffffffffu, qv, d);
            s0 += qd * Kt[d][lane];
            s1 += qd * Kt[d][lane + 32];
            s2 += qd * Kt[d][lane + 64];
        }
        s0 *= scale; s1 *= scale; s2 *= scale;
        float mx = fmaxf(s0, fmaxf(s1, s2));
        #pragma unroll
        for (int o = 16; o; o >>= 1) mx = fmaxf(mx, __shfl_xor_sync(0xffffffffu, mx, o));
        float e0 = __expf(s0 - mx), e1 = __expf(s1 - mx), e2 = __expf(s2 - mx);
        float ps = e0 + e1 + e2;
        #pragma unroll
        for (int o = 16; o; o >>= 1) ps += __shfl_xor_sync(0xffffffffu, ps, o);
        float inv = 1.f / ps;
        float acc = 0.f;
        #pragma unroll
        for (int j = 0; j < KT; j++) {
            float pj = __shfl_sync(0xffffffffu, (j < 32) ? e0 : ((j < 64) ? e1 : e2), j & 31);
            acc += pj * Vs[j][lane];
        }
        acc *= inv;
        g_att[(((size_t)bi*NN + n)*HH + h)*DD + lane] = acc;
    }
}

extern "C" void kernel_launch(void* const* d_in, const int* in_sizes, int n_in,
                              void* d_out, int out_size) {
    const float* x      = (const float*)d_in[0];
    const float* w_qkv  = (const float*)d_in[1];
    const float* w_gp   = (const float*)d_in[2];
    const float* w_proj = (const float*)d_in[3];
    float* out = (float*)d_out;

    zero_kernel<<<144, 256>>>();
    gemm_nt<0><<<dim3(9, 25), 256>>>(x, w_qkv, nullptr);       // QKV: 3200x1152x384
    route_kernel<<<NQ/8, 256>>>(w_gp);
    qmw_topk_kernel<<<BHc*(GG/GPB), 256>>>();
    attn_kernel<<<NROW, 256>>>();
    gemm_nt<1><<<dim3(3, 25), 256>>>(nullptr, w_proj, out);    // proj: 3200x384x384
}

// round 7
// speedup vs baseline: 1.2862x; 1.2720x over previous
#include <cuda_runtime.h>
#include <float.h>
#include <stdint.h>

#define BB 2
#define HH 12
#define NN 1600
#define DD 32
#define GG 48
#define KT 96
#define CC 384
#define BHc (BB*HH)          // 24
#define NQ (BHc*NN)          // 38400
#define NROW (BHc*GG)        // 1152

// Scratch (no cudaMalloc allowed)
__device__ float g_qkv[3][BHc*NN*DD];      // [which][b*h][n][d]
__device__ int   g_gidx[NQ];
__device__ float g_qsum[NROW*DD];
__device__ int   g_cnt[NROW];
__device__ int   g_topk[NROW*KT];
__device__ int   g_qlist[NROW*NN];         // query indices per (bh,g)
__device__ float g_att[BB*NN*HH*DD];       // [b][n][h][d]

__global__ void zero_kernel() {
    int i = blockIdx.x*blockDim.x + threadIdx.x;
    if (i < NROW*DD) g_qsum[i] = 0.f;
    if (i < NROW)    g_cnt[i] = 0;
}

// ---------------- 3xTF32 mma.sync GEMM ----------------
__device__ __forceinline__ uint32_t tf32_rna(float x) {
    uint32_t r; asm("cvt.rna.tf32.f32 %0, %1;" : "=r"(r) : "f"(x)); return r;
}
__device__ __forceinline__ void split_tf32(float x, uint32_t& h, uint32_t& l) {
    h = tf32_rna(x);
    l = tf32_rna(x - __uint_as_float(h));
}
__device__ __forceinline__ void mma8(float* c, const uint32_t* a, const uint32_t* b) {
    asm volatile(
        "mma.sync.aligned.m16n8k8.row.col.f32.tf32.tf32.f32 "
        "{%0,%1,%2,%3}, {%4,%5,%6,%7}, {%8,%9}, {%0,%1,%2,%3};"
        : "+f"(c[0]), "+f"(c[1]), "+f"(c[2]), "+f"(c[3])
        : "r"(a[0]), "r"(a[1]), "r"(a[2]), "r"(a[3]), "r"(b[0]), "r"(b[1]));
}

// out[m][col] = sum_k A[m][k] * B[col][k]   (NT, K=384)
// MODE 0: A = x, scatter into g_qkv.  MODE 1: A = g_att, write d_out.
// C tile 128x128 per block, 8 warps in 2(m)x4(n), warp tile 64x32.
// fp32 = tf32_hi + tf32_lo; acc += ah*bh + ah*bl + al*bh.
template<int MODE>
__global__ void __launch_bounds__(256, 1) gemm_tf32(const float* __restrict__ A,
                                                    const float* __restrict__ B,
                                                    float* __restrict__ out) {
    __shared__ float As[128][36];    // [m][k], stride 36 -> conflict-free frag loads
    __shared__ float Bs[128][36];    // [n][k]
    const int K = CC;
    const float* Ap = (MODE == 0) ? A : (const float*)g_att;
    int m0 = blockIdx.y * 128, n0 = blockIdx.x * 128;
    int tid = threadIdx.x, wid = tid >> 5, lane = tid & 31;
    int warpM = (wid >> 2) * 64;     // 0 or 64
    int warpN = (wid & 3) * 32;      // 0,32,64,96

    float acc[4][4][4];
    #pragma unroll
    for (int i = 0; i < 4; i++)
        #pragma unroll
        for (int j = 0; j < 4; j++)
            #pragma unroll
            for (int r = 0; r < 4; r++) acc[i][j][r] = 0.f;

    int srow = tid >> 3, sc4 = (tid & 7) << 2;
    for (int kt = 0; kt < K/32; kt++) {
        int k0 = kt * 32;
        #pragma unroll
        for (int it = 0; it < 4; it++) {
            int row = it*32 + srow;
            float4 va = *(const float4*)(Ap + (size_t)(m0 + row)*K + k0 + sc4);
            float4 vb = *(const float4*)(B  + (size_t)(n0 + row)*K + k0 + sc4);
            *(float4*)&As[row][sc4] = va;
            *(float4*)&Bs[row][sc4] = vb;
        }
        __syncthreads();
        #pragma unroll
        for (int kk = 0; kk < 4; kk++) {
            int c = kk*8 + (lane & 3);
            uint32_t ah[4][4], al[4][4], bh[4][2], bl[4][2];
            #pragma unroll
            for (int fm = 0; fm < 4; fm++) {
                int r = warpM + fm*16 + (lane >> 2);
                split_tf32(As[r    ][c    ], ah[fm][0], al[fm][0]);
                split_tf32(As[r + 8][c    ], ah[fm][1], al[fm][1]);
                split_tf32(As[r    ][c + 4], ah[fm][2], al[fm][2]);
                split_tf32(As[r + 8][c + 4], ah[fm][3], al[fm][3]);
            }
            #pragma unroll
            for (int fn = 0; fn < 4; fn++) {
                int n = warpN + fn*8 + (lane >> 2);
                split_tf32(Bs[n][c    ], bh[fn][0], bl[fn][0]);
                split_tf32(Bs[n][c + 4], bh[fn][1], bl[fn][1]);
            }
            #pragma unroll
            for (int fm = 0; fm < 4; fm++)
                #pragma unroll
                for (int fn = 0; fn < 4; fn++)
                    mma8(acc[fm][fn], ah[fm], bh[fn]);
            #pragma unroll
            for (int fm = 0; fm < 4; fm++)
                #pragma unroll
                for (int fn = 0; fn < 4; fn++)
                    mma8(acc[fm][fn], ah[fm], bl[fn]);
            #pragma unroll
            for (int fm = 0; fm < 4; fm++)
                #pragma unroll
                for (int fn = 0; fn < 4; fn++)
                    mma8(acc[fm][fn], al[fm], bh[fn]);
        }
        __syncthreads();
    }

    // epilogue: c0,c1 -> (m, n),(m, n+1); c2,c3 -> (m+8, n),(m+8, n+1)
    #pragma unroll
    for (int fm = 0; fm < 4; fm++) {
        #pragma unroll
        for (int half = 0; half < 2; half++) {
            int m = m0 + warpM + fm*16 + (lane >> 2) + half*8;
            int bi = m / NN, n = m % NN;
            #pragma unroll
            for (int fn = 0; fn < 4; fn++) {
                int col = n0 + warpN + fn*8 + 2*(lane & 3);
                float v0 = acc[fm][fn][half*2 + 0];
                float v1 = acc[fm][fn][half*2 + 1];
                if (MODE == 0) {
                    int which = col / (HH*DD);
                    int r2 = col % (HH*DD);
                    int head = r2 / DD, dd = r2 % DD;
                    float* dst = &g_qkv[which][(((size_t)bi*HH + head)*NN + n)*DD + dd];
                    *(float2*)dst = make_float2(v0, v1);
                } else {
                    *(float2*)&out[(size_t)m*(HH*DD) + col] = make_float2(v0, v1);
                }
            }
        }
    }
}

// One warp per query. Lane-per-group argmax (first-max tie-break = jnp.argmax),
// accumulate group sums/counts, append query to its group's list.
__global__ void route_kernel(const float* __restrict__ w_gp) {
    __shared__ float sgp[GG][33];
    int tid = threadIdx.x;
    int qid = blockIdx.x * 8 + (tid >> 5);
    int lane = tid & 31;
    int bh = qid / NN, n = qid % NN;
    int h = bh % HH;
    for (int i = tid; i < GG*DD; i += 256)
        sgp[i >> 5][i & 31] = w_gp[h*GG*DD + i];
    __syncthreads();
    float qv = g_qkv[0][((size_t)bh*NN + n)*DD + lane];
    float s0 = 0.f, s1 = 0.f;
    #pragma unroll
    for (int d = 0; d < DD; d++) {
        float qd = __shfl_sync(0xffffffffu, qv, d);
        s0 += qd * sgp[lane][d];
        if (lane < 16) s1 += qd * sgp[lane + 32][d];
    }
    float bv = s0; int bg = lane;
    if (lane < 16 && (s1 > bv)) { bv = s1; bg = lane + 32; }
    #pragma unroll
    for (int o = 16; o; o >>= 1) {
        float ov = __shfl_xor_sync(0xffffffffu, bv, o);
        int   og = __shfl_xor_sync(0xffffffffu, bg, o);
        if (ov > bv || (ov == bv && og < bg)) { bv = ov; bg = og; }
    }
    bg = __shfl_sync(0xffffffffu, bg, 0);
    int row = bh*GG + bg;
    if (lane == 0) {
        g_gidx[qid] = bg;
        int p = atomicAdd(&g_cnt[row], 1);
        g_qlist[row*NN + p] = n;
    }
    atomicAdd(&g_qsum[row*DD + lane], qv);
}

__device__ __forceinline__ unsigned f2u_mono(float f) {
    unsigned u = __float_as_uint(f);
    return u ^ (((int)u >> 31) | 0x80000000u);
}

// One block per (bh, 4 groups): fold qmean, compute qmw scores, radix-select top-96.
// Empty groups are skipped entirely (their topk list is never consumed).
#define GPB 4
__global__ void qmw_topk_kernel() {
    int blk = blockIdx.x;                 // [0, BHc * GG/GPB) = 288
    int bh = blk / (GG/GPB);
    int g0 = (blk % (GG/GPB)) * GPB;
    __shared__ float qm[GPB][DD];
    __shared__ unsigned uv[GPB][NN];
    __shared__ unsigned hist[256];
    __shared__ int s_selb, s_k, s_nout;
    __shared__ int warp_sums[8];
    __shared__ int s_cnt[GPB];
    int tid = threadIdx.x, lane = tid & 31, w = tid >> 5;

    if (tid < GPB) s_cnt[tid] = g_cnt[bh*GG + g0 + tid];
    if (tid < GPB*DD) {
        int row = bh*GG + g0 + tid/DD;
        float c = (float)g_cnt[row];
        qm[tid/DD][tid & 31] = g_qsum[row*DD + (tid & 31)] / fmaxf(c, 1e-8f);
    }
    __syncthreads();

    const float* kb = &g_qkv[1][(size_t)bh*NN*DD];
    for (int m = tid; m < NN; m += 256) {
        float kr[DD];
        #pragma unroll
        for (int t = 0; t < 8; t++) {
            float4 v = *(const float4*)(kb + (size_t)m*DD + 4*t);
            kr[4*t] = v.x; kr[4*t+1] = v.y; kr[4*t+2] = v.z; kr[4*t+3] = v.w;
        }
        #pragma unroll
        for (int g = 0; g < GPB; g++) {
            float s = 0.f;
            #pragma unroll
            for (int d = 0; d < DD; d++) s += qm[g][d] * kr[d];
            uv[g][m] = f2u_mono(s);
        }
    }
    __syncthreads();

    for (int g = 0; g < GPB; g++) {
        if (s_cnt[g] == 0) continue;      // uniform across block: group unused
        int row = bh*GG + g0 + g;
        unsigned prefix = 0;
        int k = KT;
        #pragma unroll
        for (int pass = 0; pass < 4; pass++) {
            int shift = 24 - 8*pass;
            hist[tid] = 0;
            __syncthreads();
            for (int m = tid; m < NN; m += 256) {
                unsigned u = uv[g][m];
                bool cand = (pass == 0) || ((u >> (shift+8)) == (prefix >> (shift+8)));
                if (cand) atomicAdd(&hist[(u >> shift) & 255], 1u);
            }
            __syncthreads();
            if (tid < 32) {
                unsigned hv[8], loc[8];
                unsigned s = 0;
                #pragma unroll
                for (int i = 7; i >= 0; i--) {
                    hv[i] = hist[lane*8 + i];
                    s += hv[i];
                    loc[i] = s;
                }
                unsigned run = s;
                #pragma unroll
                for (int o = 1; o < 32; o <<= 1) {
                    unsigned t = __shfl_down_sync(0xffffffffu, run, o);
                    if (lane + o < 32) run += t;
                }
                unsigned above = run - s;
                #pragma unroll
                for (int i = 0; i < 8; i++) {
                    unsigned S  = above + loc[i];
                    unsigned gt = S - hv[i];
                    if ((unsigned)k <= S && (unsigned)k > gt) {
                        s_selb = lane*8 + i;
                        s_k    = k - (int)gt;
                    }
                }
            }
            __syncthreads();
            prefix |= (unsigned)s_selb << shift;
            k = s_k;
            __syncthreads();
        }
        unsigned uT = prefix;
        int k_rem = k;
        if (tid == 0) s_nout = 0;
        __syncthreads();
        for (int m = tid; m < NN; m += 256) {
            if (uv[g][m] > uT) {
                int p = atomicAdd(&s_nout, 1);
                g_topk[row*KT + p] = m;
            }
        }
        __syncthreads();
        int base = s_nout;
        const int CH = (NN + 255) / 256;
        int lo = tid * CH;
        int hi = lo + CH; if (hi > NN) hi = NN; if (lo > NN) lo = NN;
        int c_loc = 0;
        for (int m = lo; m < hi; m++) if (uv[g][m] == uT) c_loc++;
        int v = c_loc;
        #pragma unroll
        for (int o = 1; o < 32; o <<= 1) {
            int t = __shfl_up_sync(0xffffffffu, v, o);
            if (lane >= o) v += t;
        }
        if (lane == 31) warp_sums[w] = v;
        __syncthreads();
        int woff = 0;
        #pragma unroll
        for (int ww = 0; ww < 8; ww++) if (ww < w) woff += warp_sums[ww];
        int rank = woff + v - c_loc;
        for (int m = lo; m < hi; m++) {
            if (uv[g][m] == uT) {
                if (rank < k_rem) g_topk[row*KT + base + rank] = m;
                rank++;
            }
        }
        __syncthreads();
    }
}

// One block per (bh,g): stage the group's 96 K/V rows in smem, then each warp
// processes queries of the group: scores + softmax + weighted V sum.
__global__ void attn_kernel() {
    int row = blockIdx.x;              // [0, NROW)
    int cnt = g_cnt[row];
    if (cnt == 0) return;
    int bh = row / GG;
    int bi = bh / HH, h = bh % HH;
    __shared__ float Kt[DD][97];       // [d][key]
    __shared__ float Vs[KT][33];       // [key][d]
    int tid = threadIdx.x, w = tid >> 5, lane = tid & 31;
    const int* tk = &g_topk[row*KT];
    const float* kb = &g_qkv[1][(size_t)bh*NN*DD];
    const float* vb = &g_qkv[2][(size_t)bh*NN*DD];
    for (int j = w; j < KT; j += 8) {
        int idx = tk[j];
        Kt[lane][j] = kb[(size_t)idx*DD + lane];
        Vs[j][lane] = vb[(size_t)idx*DD + lane];
    }
    __syncthreads();
    const int* ql = &g_qlist[row*NN];
    const float* qb = &g_qkv[0][(size_t)bh*NN*DD];
    const float scale = 0.17677669529663687f;  // 32^-0.5
    for (int i = w; i < cnt; i += 8) {
        int n = ql[i];
        float qv = qb[(size_t)n*DD + lane];
        float s0 = 0.f, s1 = 0.f, s2 = 0.f;
        #pragma unroll
        for (int d = 0; d < DD; d++) {
            float qd = __shfl_sync(0xffffffffu, qv, d);
            s0 += qd * Kt[d][lane];
            s1 += qd * Kt[d][lane + 32];
            s2 += qd * Kt[d][lane + 64];
        }
        s0 *= scale; s1 *= scale; s2 *= scale;
        float mx = fmaxf(s0, fmaxf(s1, s2));
        #pragma unroll
        for (int o = 16; o; o >>= 1) mx = fmaxf(mx, __shfl_xor_sync(0xffffffffu, mx, o));
        float e0 = __expf(s0 - mx), e1 = __expf(s1 - mx), e2 = __expf(s2 - mx);
        float ps = e0 + e1 + e2;
        #pragma unroll
        for (int o = 16; o; o >>= 1) ps += __shfl_xor_sync(0xffffffffu, ps, o);
        float inv = 1.f / ps;
        float acc = 0.f;
        #pragma unroll
        for (int j = 0; j < KT; j++) {
            float pj = __shfl_sync(0xffffffffu, (j < 32) ? e0 : ((j < 64) ? e1 : e2), j & 31);
            acc += pj * Vs[j][lane];
        }
        acc *= inv;
        g_att[(((size_t)bi*NN + n)*HH + h)*DD + lane] = acc;
    }
}

extern "C" void kernel_launch(void* const* d_in, const int* in_sizes, int n_in,
                              void* d_out, int out_size) {
    const float* x      = (const float*)d_in[0];
    const float* w_qkv  = (const float*)d_in[1];
    const float* w_gp   = (const float*)d_in[2];
    const float* w_proj = (const float*)d_in[3];
    float* out = (float*)d_out;

    zero_kernel<<<144, 256>>>();
    gemm_tf32<0><<<dim3(9, 25), 256>>>(x, w_qkv, nullptr);       // QKV: 3200x1152x384
    route_kernel<<<NQ/8, 256>>>(w_gp);
    qmw_topk_kernel<<<BHc*(GG/GPB), 256>>>();
    attn_kernel<<<NROW, 256>>>();
    gemm_tf32<1><<<dim3(3, 25), 256>>>(nullptr, w_proj, out);    // proj: 3200x384x384
}

// round 8
// speedup vs baseline: 1.4182x; 1.1027x over previous
#include <cuda_runtime.h>
#include <float.h>
#include <stdint.h>

#define BB 2
#define HH 12
#define NN 1600
#define DD 32
#define GG 48
#define KT 96
#define CC 384
#define BHc (BB*HH)          // 24
#define NQ (BHc*NN)          // 38400
#define NROW (BHc*GG)        // 1152

// Scratch (no cudaMalloc allowed)
__device__ float g_qkv[3][BHc*NN*DD];      // [which][b*h][n][d]
__device__ int   g_gidx[NQ];
__device__ float g_qsum[NROW*DD];
__device__ int   g_cnt[NROW];
__device__ int   g_topk[NROW*KT];
__device__ int   g_qlist[NROW*NN];         // query indices per (bh,g)
__device__ float g_att[BB*NN*HH*DD];       // [b][n][h][d]
__device__ unsigned g_scores[NROW*NN];     // f2u-mapped qmw scores

__global__ void zero_kernel() {
    int i = blockIdx.x*blockDim.x + threadIdx.x;
    if (i < NROW*DD) g_qsum[i] = 0.f;
    if (i < NROW)    g_cnt[i] = 0;
}

// ---------------- 3xTF32 mma.sync GEMM ----------------
__device__ __forceinline__ uint32_t tf32_rna(float x) {
    uint32_t r; asm("cvt.rna.tf32.f32 %0, %1;" : "=r"(r) : "f"(x)); return r;
}
__device__ __forceinline__ void split_tf32(float x, uint32_t& h, uint32_t& l) {
    h = tf32_rna(x);
    l = tf32_rna(x - __uint_as_float(h));
}
__device__ __forceinline__ void mma8(float* c, const uint32_t* a, const uint32_t* b) {
    asm volatile(
        "mma.sync.aligned.m16n8k8.row.col.f32.tf32.tf32.f32 "
        "{%0,%1,%2,%3}, {%4,%5,%6,%7}, {%8,%9}, {%0,%1,%2,%3};"
        : "+f"(c[0]), "+f"(c[1]), "+f"(c[2]), "+f"(c[3])
        : "r"(a[0]), "r"(a[1]), "r"(a[2]), "r"(a[3]), "r"(b[0]), "r"(b[1]));
}

// out[m][col] = sum_k A[m][k] * B[col][k]   (NT, K=384)
// MODE 0: A = x, scatter into g_qkv.  MODE 1: A = g_att, write d_out.
// C tile 128x128 per block, 8 warps in 2(m)x4(n), warp tile 64x32.
// fp32 = tf32_hi + tf32_lo; acc += ah*bh + ah*bl + al*bh.
template<int MODE>
__global__ void __launch_bounds__(256, 1) gemm_tf32(const float* __restrict__ A,
                                                    const float* __restrict__ B,
                                                    float* __restrict__ out) {
    __shared__ float As[128][36];    // [m][k], stride 36 -> conflict-free frag loads
    __shared__ float Bs[128][36];    // [n][k]
    const int K = CC;
    const float* Ap = (MODE == 0) ? A : (const float*)g_att;
    int m0 = blockIdx.y * 128, n0 = blockIdx.x * 128;
    int tid = threadIdx.x, wid = tid >> 5, lane = tid & 31;
    int warpM = (wid >> 2) * 64;     // 0 or 64
    int warpN = (wid & 3) * 32;      // 0,32,64,96

    float acc[4][4][4];
    #pragma unroll
    for (int i = 0; i < 4; i++)
        #pragma unroll
        for (int j = 0; j < 4; j++)
            #pragma unroll
            for (int r = 0; r < 4; r++) acc[i][j][r] = 0.f;

    int srow = tid >> 3, sc4 = (tid & 7) << 2;
    for (int kt = 0; kt < K/32; kt++) {
        int k0 = kt * 32;
        #pragma unroll
        for (int it = 0; it < 4; it++) {
            int row = it*32 + srow;
            float4 va = *(const float4*)(Ap + (size_t)(m0 + row)*K + k0 + sc4);
            float4 vb = *(const float4*)(B  + (size_t)(n0 + row)*K + k0 + sc4);
            *(float4*)&As[row][sc4] = va;
            *(float4*)&Bs[row][sc4] = vb;
        }
        __syncthreads();
        #pragma unroll
        for (int kk = 0; kk < 4; kk++) {
            int c = kk*8 + (lane & 3);
            uint32_t ah[4][4], al[4][4], bh[4][2], bl[4][2];
            #pragma unroll
            for (int fm = 0; fm < 4; fm++) {
                int r = warpM + fm*16 + (lane >> 2);
                split_tf32(As[r    ][c    ], ah[fm][0], al[fm][0]);
                split_tf32(As[r + 8][c    ], ah[fm][1], al[fm][1]);
                split_tf32(As[r    ][c + 4], ah[fm][2], al[fm][2]);
                split_tf32(As[r + 8][c + 4], ah[fm][3], al[fm][3]);
            }
            #pragma unroll
            for (int fn = 0; fn < 4; fn++) {
                int n = warpN + fn*8 + (lane >> 2);
                split_tf32(Bs[n][c    ], bh[fn][0], bl[fn][0]);
                split_tf32(Bs[n][c + 4], bh[fn][1], bl[fn][1]);
            }
            #pragma unroll
            for (int fm = 0; fm < 4; fm++)
                #pragma unroll
                for (int fn = 0; fn < 4; fn++)
                    mma8(acc[fm][fn], ah[fm], bh[fn]);
            #pragma unroll
            for (int fm = 0; fm < 4; fm++)
                #pragma unroll
                for (int fn = 0; fn < 4; fn++)
                    mma8(acc[fm][fn], ah[fm], bl[fn]);
            #pragma unroll
            for (int fm = 0; fm < 4; fm++)
                #pragma unroll
                for (int fn = 0; fn < 4; fn++)
                    mma8(acc[fm][fn], al[fm], bh[fn]);
        }
        __syncthreads();
    }

    // epilogue: c0,c1 -> (m, n),(m, n+1); c2,c3 -> (m+8, n),(m+8, n+1)
    #pragma unroll
    for (int fm = 0; fm < 4; fm++) {
        #pragma unroll
        for (int half = 0; half < 2; half++) {
            int m = m0 + warpM + fm*16 + (lane >> 2) + half*8;
            int bi = m / NN, n = m % NN;
            #pragma unroll
            for (int fn = 0; fn < 4; fn++) {
                int col = n0 + warpN + fn*8 + 2*(lane & 3);
                float v0 = acc[fm][fn][half*2 + 0];
                float v1 = acc[fm][fn][half*2 + 1];
                if (MODE == 0) {
                    int which = col / (HH*DD);
                    int r2 = col % (HH*DD);
                    int head = r2 / DD, dd = r2 % DD;
                    float* dst = &g_qkv[which][(((size_t)bi*HH + head)*NN + n)*DD + dd];
                    *(float2*)dst = make_float2(v0, v1);
                } else {
                    *(float2*)&out[(size_t)m*(HH*DD) + col] = make_float2(v0, v1);
                }
            }
        }
    }
}

// One warp per query. Lane-per-group argmax (first-max tie-break = jnp.argmax),
// accumulate group sums/counts, append query to its group's list.
__global__ void route_kernel(const float* __restrict__ w_gp) {
    __shared__ float sgp[GG][33];
    int tid = threadIdx.x;
    int qid = blockIdx.x * 8 + (tid >> 5);
    int lane = tid & 31;
    int bh = qid / NN, n = qid % NN;
    int h = bh % HH;
    for (int i = tid; i < GG*DD; i += 256)
        sgp[i >> 5][i & 31] = w_gp[h*GG*DD + i];
    __syncthreads();
    float qv = g_qkv[0][((size_t)bh*NN + n)*DD + lane];
    float s0 = 0.f, s1 = 0.f;
    #pragma unroll
    for (int d = 0; d < DD; d++) {
        float qd = __shfl_sync(0xffffffffu, qv, d);
        s0 += qd * sgp[lane][d];
        if (lane < 16) s1 += qd * sgp[lane + 32][d];
    }
    float bv = s0; int bg = lane;
    if (lane < 16 && (s1 > bv)) { bv = s1; bg = lane + 32; }
    #pragma unroll
    for (int o = 16; o; o >>= 1) {
        float ov = __shfl_xor_sync(0xffffffffu, bv, o);
        int   og = __shfl_xor_sync(0xffffffffu, bg, o);
        if (ov > bv || (ov == bv && og < bg)) { bv = ov; bg = og; }
    }
    bg = __shfl_sync(0xffffffffu, bg, 0);
    int row = bh*GG + bg;
    if (lane == 0) {
        g_gidx[qid] = bg;
        int p = atomicAdd(&g_cnt[row], 1);
        g_qlist[row*NN + p] = n;
    }
    atomicAdd(&g_qsum[row*DD + lane], qv);
}

__device__ __forceinline__ unsigned f2u_mono(float f) {
    unsigned u = __float_as_uint(f);
    return u ^ (((int)u >> 31) | 0x80000000u);
}

// Grid (8, BHc): each block computes qmw scores for 200 keys x all 48 groups of one bh.
// K is read once per key; dot order (d sequential) identical to previous rounds.
__global__ void qmw_score_kernel() {
    __shared__ float qm[GG][DD];
    int bh = blockIdx.y;
    int n0 = blockIdx.x * 200;
    int tid = threadIdx.x;
    for (int i = tid; i < GG*DD; i += 256) {
        int g = i >> 5, d = i & 31;
        int row = bh*GG + g;
        float c = (float)g_cnt[row];
        qm[g][d] = g_qsum[row*DD + d] / fmaxf(c, 1e-8f);
    }
    __syncthreads();
    const float* kb = &g_qkv[1][(size_t)bh*NN*DD];
    for (int m = n0 + tid; m < n0 + 200; m += 256) {
        float kr[DD];
        #pragma unroll
        for (int t = 0; t < 8; t++) {
            float4 v = *(const float4*)(kb + (size_t)m*DD + 4*t);
            kr[4*t] = v.x; kr[4*t+1] = v.y; kr[4*t+2] = v.z; kr[4*t+3] = v.w;
        }
        #pragma unroll 4
        for (int g = 0; g < GG; g++) {
            float s = 0.f;
            #pragma unroll
            for (int d = 0; d < DD; d++) s += qm[g][d] * kr[d];
            g_scores[(size_t)(bh*GG + g)*NN + m] = f2u_mono(s);
        }
    }
}

// One block per row: radix-select top-96 from g_scores[row].
// Empty rows exit immediately (their topk list is never consumed).
__global__ void topk_select_kernel() {
    int row = blockIdx.x;
    if (g_cnt[row] == 0) return;
    __shared__ unsigned uv[NN];
    __shared__ unsigned hist[256];
    __shared__ int s_selb, s_k, s_nout;
    __shared__ int warp_sums[8];
    int tid = threadIdx.x, lane = tid & 31, w = tid >> 5;

    const unsigned* src = &g_scores[(size_t)row*NN];
    for (int m = tid; m < NN; m += 256) uv[m] = src[m];
    hist[tid] = 0;
    __syncthreads();

    unsigned prefix = 0;
    int k = KT;
    #pragma unroll
    for (int pass = 0; pass < 4; pass++) {
        int shift = 24 - 8*pass;
        for (int m = tid; m < NN; m += 256) {
            unsigned u = uv[m];
            bool cand = (pass == 0) || ((u >> (shift+8)) == (prefix >> (shift+8)));
            if (cand) atomicAdd(&hist[(u >> shift) & 255], 1u);
        }
        __syncthreads();
        if (tid < 32) {
            // lane owns bins [lane*8, lane*8+8): within-lane suffix sums
            unsigned hv[8], loc[8];
            unsigned s = 0;
            #pragma unroll
            for (int i = 7; i >= 0; i--) {
                hv[i] = hist[lane*8 + i];
                s += hv[i];
                loc[i] = s;
            }
            unsigned run = s;
            #pragma unroll
            for (int o = 1; o < 32; o <<= 1) {
                unsigned t = __shfl_down_sync(0xffffffffu, run, o);
                if (lane + o < 32) run += t;
            }
            unsigned above = run - s;  // count in lanes > me
            #pragma unroll
            for (int i = 0; i < 8; i++) {
                unsigned S  = above + loc[i];           // count >= bin
                unsigned gt = S - hv[i];                // count > bin
                if ((unsigned)k <= S && (unsigned)k > gt) {
                    s_selb = lane*8 + i;
                    s_k    = k - (int)gt;
                }
            }
        }
        __syncthreads();
        prefix |= (unsigned)s_selb << shift;
        k = s_k;
        hist[tid] = 0;                 // re-zero for next pass
        __syncthreads();
    }
    unsigned uT = prefix;
    int k_rem = k;
    if (tid == 0) s_nout = 0;
    __syncthreads();
    // strictly-greater: order in g_topk is irrelevant (mask semantics)
    for (int m = tid; m < NN; m += 256) {
        if (uv[m] > uT) {
            int p = atomicAdd(&s_nout, 1);
            g_topk[row*KT + p] = m;
        }
    }
    __syncthreads();
    int base = s_nout;                 // == KT - k_rem
    // equals: keep the k_rem LOWEST indices (lax.top_k stable tie-break).
    const int CH = (NN + 255) / 256;   // 7
    int lo = tid * CH;
    int hi = lo + CH; if (hi > NN) hi = NN; if (lo > NN) lo = NN;
    int c_loc = 0;
    for (int m = lo; m < hi; m++) if (uv[m] == uT) c_loc++;
    int v = c_loc;
    #pragma unroll
    for (int o = 1; o < 32; o <<= 1) {
        int t = __shfl_up_sync(0xffffffffu, v, o);
        if (lane >= o) v += t;
    }
    if (lane == 31) warp_sums[w] = v;
    __syncthreads();
    int woff = 0;
    #pragma unroll
    for (int ww = 0; ww < 8; ww++) if (ww < w) woff += warp_sums[ww];
    int rank = woff + v - c_loc;       // exclusive prefix in index order
    for (int m = lo; m < hi; m++) {
        if (uv[m] == uT) {
            if (rank < k_rem) g_topk[row*KT + base + rank] = m;
            rank++;
        }
    }
}

// One block per (bh,g): stage the group's 96 K/V rows in smem, then each warp
// processes queries of the group: scores + softmax + weighted V sum.
__global__ void attn_kernel() {
    int row = blockIdx.x;              // [0, NROW)
    int cnt = g_cnt[row];
    if (cnt == 0) return;
    int bh = row / GG;
    int bi = bh / HH, h = bh % HH;
    __shared__ float Kt[DD][97];       // [d][key]
    __shared__ float Vs[KT][33];       // [key][d]
    int tid = threadIdx.x, w = tid >> 5, lane = tid & 31;
    const int* tk = &g_topk[row*KT];
    const float* kb = &g_qkv[1][(size_t)bh*NN*DD];
    const float* vb = &g_qkv[2][(size_t)bh*NN*DD];
    for (int j = w; j < KT; j += 8) {
        int idx = tk[j];
        Kt[lane][j] = kb[(size_t)idx*DD + lane];
        Vs[j][lane] = vb[(size_t)idx*DD + lane];
    }
    __syncthreads();
    const int* ql = &g_qlist[row*NN];
    const float* qb = &g_qkv[0][(size_t)bh*NN*DD];
    const float scale = 0.17677669529663687f;  // 32^-0.5
    for (int i = w; i < cnt; i += 8) {
        int n = ql[i];
        float qv = qb[(size_t)n*DD + lane];
        float s0 = 0.f, s1 = 0.f, s2 = 0.f;
        #pragma unroll
        for (int d = 0; d < DD; d++) {
            float qd = __shfl_sync(0xffffffffu, qv, d);
            s0 += qd * Kt[d][lane];
            s1 += qd * Kt[d][lane + 32];
            s2 += qd * Kt[d][lane + 64];
        }
        s0 *= scale; s1 *= scale; s2 *= scale;
        float mx = fmaxf(s0, fmaxf(s1, s2));
        #pragma unroll
        for (int o = 16; o; o >>= 1) mx = fmaxf(mx, __shfl_xor_sync(0xffffffffu, mx, o));
        float e0 = __expf(s0 - mx), e1 = __expf(s1 - mx), e2 = __expf(s2 - mx);
        float ps = e0 + e1 + e2;
        #pragma unroll
        for (int o = 16; o; o >>= 1) ps += __shfl_xor_sync(0xffffffffu, ps, o);
        float inv = 1.f / ps;
        float acc = 0.f;
        #pragma unroll
        for (int j = 0; j < KT; j++) {
            float pj = __shfl_sync(0xffffffffu, (j < 32) ? e0 : ((j < 64) ? e1 : e2), j & 31);
            acc += pj * Vs[j][lane];
        }
        acc *= inv;
        g_att[(((size_t)bi*NN + n)*HH + h)*DD + lane] = acc;
    }
}

extern "C" void kernel_launch(void* const* d_in, const int* in_sizes, int n_in,
                              void* d_out, int out_size) {
    const float* x      = (const float*)d_in[0];
    const float* w_qkv  = (const float*)d_in[1];
    const float* w_gp   = (const float*)d_in[2];
    const float* w_proj = (const float*)d_in[3];
    float* out = (float*)d_out;

    zero_kernel<<<144, 256>>>();
    gemm_tf32<0><<<dim3(9, 25), 256>>>(x, w_qkv, nullptr);       // QKV: 3200x1152x384
    route_kernel<<<NQ/8, 256>>>(w_gp);
    qmw_score_kernel<<<dim3(8, BHc), 256>>>();
    topk_select_kernel<<<NROW, 256>>>();
    attn_kernel<<<NROW, 256>>>();
    gemm_tf32<1><<<dim3(3, 25), 256>>>(nullptr, w_proj, out);    // proj: 3200x384x384
}